// round 1
// baseline (speedup 1.0000x reference)
#include <cuda_runtime.h>
#include <math.h>

#define NMODES 2
#define STEPN  5
#define DTAPS  1001
#define NTAPS  101
#define HID    100
#define TRIM   50
#define Bz     4
#define SEQ    500000
#define FS_NOM 160000000000.0f

#define TILE_OUT 1024
#define KO       4
#define NTILE    256

// ---------------- scratch (static device memory; no allocations) ----------------
// Two ping-pong signal buffers: [2][B*NMODES][SEQ] as float2 (re,im). 64 MB total.
__device__ float2 g_buf[2][Bz * NMODES * SEQ];
__device__ float  g_hr[Bz][DTAPS];
__device__ float  g_hi[Bz][DTAPS];
__device__ float  g_Nk[Bz][4][NTAPS];   // [b][m*2+n][t]
__device__ float  g_coef[Bz];

// ---------------- setup: dispersion kernel via direct inverse DFT ----------------
// Mimics: phase computed in float32 (as JAX does), kf = exp(-i*phase) complex64,
// h = fftshift(ifft(kf)).
__global__ void disp_kernel(const float* __restrict__ task_info) {
    int m = blockIdx.x;      // output tap index (pre-shift)
    int b = blockIdx.y;

    const double c_kms = 299792.458;
    const double FCd   = 299792458.0 / 1.55e-6;
    const double lamb  = c_kms / FCd;
    const double beta2 = -(16.5 * lamb * lamb) / (2.0 * 3.14159265358979323846 * c_kms) / 1000.0;

    float Fsf = task_info[b * 4 + 2];
    float t1  = (float)(2.0 * 3.14159265358979323846) * Fsf;   // 2*pi*Fs in f32
    float b2h = (float)(beta2 * 0.5);
    float dzf = -400000.0f;                                    // dz = -DZ

    double sr = 0.0, si = 0.0;
    for (int k = threadIdx.x; k < DTAPS; k += blockDim.x) {
        // np.fft.fftfreq(1001) in float32
        double fkd = (k <= DTAPS / 2) ? (double)k / (double)DTAPS
                                      : (double)(k - DTAPS) / (double)DTAPS;
        float fkf = (float)fkd;
        float om  = t1 * fkf;
        float phase = (b2h * (om * om)) * dzf;   // float32 chain, matches reference

        float cs, sn;
        sincosf(phase, &sn, &cs);                // kf = cs - i*sn

        int r = (k * m) % DTAPS;
        float ang = (float)((2.0 * 3.14159265358979323846 / (double)DTAPS) * (double)r);
        float st, ct;
        sincosf(ang, &st, &ct);                  // e^{+i*2pi*k*m/N}

        // (cs - i sn)(ct + i st)
        sr += (double)(cs * ct + sn * st);
        si += (double)(cs * st - sn * ct);
    }

    __shared__ double rr[128], ri[128];
    rr[threadIdx.x] = sr;
    ri[threadIdx.x] = si;
    __syncthreads();
    for (int o = 64; o > 0; o >>= 1) {
        if (threadIdx.x < o) {
            rr[threadIdx.x] += rr[threadIdx.x + o];
            ri[threadIdx.x] += ri[threadIdx.x + o];
        }
        __syncthreads();
    }
    if (threadIdx.x == 0) {
        int j = (m + DTAPS / 2) % DTAPS;         // fftshift
        g_hr[b][j] = (float)(rr[0] / (double)DTAPS);
        g_hi[b][j] = (float)(ri[0] / (double)DTAPS);
    }
}

// ---------------- setup: nonlinear MLP kernel + coef ----------------
__global__ void nlk_kernel(const float* __restrict__ task_info,
                           const float* __restrict__ W1, const float* __restrict__ b1,
                           const float* __restrict__ W2, const float* __restrict__ b2) {
    int b = blockIdx.x;
    int t = threadIdx.x;
    if (t == 0) {
        float P = 0.001f * powf(10.0f, task_info[b * 4 + 0] / 10.0f) / (float)NMODES;
        g_coef[b] = (float)(0.0016567 * 400000.0) * P;   // GAMMA*DZ*P
    }
    if (t < NTAPS) {
        float Fsn = task_info[b * 4 + 2] / FS_NOM;
        float Ts  = 1.0f / Fsn;
        float Ts2 = Ts * Ts;
        float pos = fabsf((float)(t - TRIM)) * 0.005f;   // * 1/200
        float inp = pos * Ts2;
        float acc0 = b2[0], acc1 = b2[1], acc2 = b2[2], acc3 = b2[3];
        for (int j = 0; j < HID; j++) {
            float h = fmaf(inp, W1[j], b1[j]);
            h = fmaxf(h, 0.0f);
            acc0 = fmaf(h, W2[j * 4 + 0], acc0);
            acc1 = fmaf(h, W2[j * 4 + 1], acc1);
            acc2 = fmaf(h, W2[j * 4 + 2], acc2);
            acc3 = fmaf(h, W2[j * 4 + 3], acc3);
        }
        float e = expf(-inp);
        g_Nk[b][0][t] = Ts2 * acc0 * e;
        g_Nk[b][1][t] = Ts2 * acc1 * e;
        g_Nk[b][2][t] = Ts2 * acc2 * e;
        g_Nk[b][3][t] = Ts2 * acc3 * e;
    }
}

// ---------------- transpose input [B,SEQ,M] -> buf0 [B*M][SEQ] interleaved ----------------
__global__ void transpose_in(const float* __restrict__ xr, const float* __restrict__ xi) {
    long i = (long)blockIdx.x * blockDim.x + threadIdx.x;   // over B*SEQ*NMODES
    long total = (long)Bz * SEQ * NMODES;
    if (i < total) {
        int  m = (int)(i % NMODES);
        long s = (i / NMODES) % SEQ;
        int  b = (int)(i / ((long)NMODES * SEQ));
        g_buf[0][(long)(b * NMODES + m) * SEQ + s] = make_float2(xr[i], xi[i]);
    }
}

// ---------------- dispersion: 1001-tap complex correlation, buf0 -> buf1 ----------------
__global__ void __launch_bounds__(256) disp_conv(int L_in) {
    int ch = blockIdx.y;          // b*2+m
    int b  = ch >> 1;
    int L_out = L_in - (DTAPS - 1);
    int base = blockIdx.x * TILE_OUT;

    __shared__ float2 sx[TILE_OUT + DTAPS - 1];  // 2024 * 8B
    __shared__ float2 sh[DTAPS];                 // 1001 * 8B

    const float2* __restrict__ x = &g_buf[0][(long)ch * SEQ];
    for (int i = threadIdx.x; i < TILE_OUT + DTAPS - 1; i += 256) {
        int g = base + i;
        sx[i] = (g < L_in) ? x[g] : make_float2(0.0f, 0.0f);
    }
    for (int i = threadIdx.x; i < DTAPS; i += 256)
        sh[i] = make_float2(g_hr[b][i], g_hi[b][i]);
    __syncthreads();

    float ar0 = 0.f, ar1 = 0.f, ar2 = 0.f, ar3 = 0.f;
    float ai0 = 0.f, ai1 = 0.f, ai2 = 0.f, ai3 = 0.f;
    int t0 = threadIdx.x;

#pragma unroll 4
    for (int t = 0; t < DTAPS; ++t) {
        float2 h = sh[t];
        float2 v0 = sx[t + t0];
        float2 v1 = sx[t + t0 + 256];
        float2 v2 = sx[t + t0 + 512];
        float2 v3 = sx[t + t0 + 768];
        ar0 = fmaf(v0.x, h.x, ar0); ar0 = fmaf(-v0.y, h.y, ar0);
        ai0 = fmaf(v0.x, h.y, ai0); ai0 = fmaf( v0.y, h.x, ai0);
        ar1 = fmaf(v1.x, h.x, ar1); ar1 = fmaf(-v1.y, h.y, ar1);
        ai1 = fmaf(v1.x, h.y, ai1); ai1 = fmaf( v1.y, h.x, ai1);
        ar2 = fmaf(v2.x, h.x, ar2); ar2 = fmaf(-v2.y, h.y, ar2);
        ai2 = fmaf(v2.x, h.y, ai2); ai2 = fmaf( v2.y, h.x, ai2);
        ar3 = fmaf(v3.x, h.x, ar3); ar3 = fmaf(-v3.y, h.y, ar3);
        ai3 = fmaf(v3.x, h.y, ai3); ai3 = fmaf( v3.y, h.x, ai3);
    }

    float2* __restrict__ ao = &g_buf[1][(long)ch * SEQ];
    int o;
    o = base + t0;       if (o < L_out) ao[o] = make_float2(ar0, ai0);
    o = base + t0 + 256; if (o < L_out) ao[o] = make_float2(ar1, ai1);
    o = base + t0 + 512; if (o < L_out) ao[o] = make_float2(ar2, ai2);
    o = base + t0 + 768; if (o < L_out) ao[o] = make_float2(ar3, ai3);
}

// ---------------- nonlinear: power conv + rotation, buf1 -> buf0 ----------------
__global__ void __launch_bounds__(256) nl_step(int A_len) {
    int b = blockIdx.y;
    int L_out = A_len - (NTAPS - 1);
    int base = blockIdx.x * NTILE;

    __shared__ float sp[2][NTILE + NTAPS - 1];   // power per mode
    __shared__ float sk[4][NTAPS];

    const float2* __restrict__ a0 = &g_buf[1][(long)(b * 2 + 0) * SEQ];
    const float2* __restrict__ a1 = &g_buf[1][(long)(b * 2 + 1) * SEQ];

    for (int i = threadIdx.x; i < NTILE + NTAPS - 1; i += 256) {
        int g = base + i;
        float2 v0 = (g < A_len) ? a0[g] : make_float2(0.f, 0.f);
        float2 v1 = (g < A_len) ? a1[g] : make_float2(0.f, 0.f);
        sp[0][i] = v0.x * v0.x + v0.y * v0.y;
        sp[1][i] = v1.x * v1.x + v1.y * v1.y;
    }
    for (int i = threadIdx.x; i < 4 * NTAPS; i += 256)
        sk[i / NTAPS][i % NTAPS] = g_Nk[b][i / NTAPS][i % NTAPS];
    __syncthreads();

    int s = base + threadIdx.x;
    float phi0 = 0.f, phi1 = 0.f;
#pragma unroll 4
    for (int t = 0; t < NTAPS; t++) {
        float p0 = sp[0][threadIdx.x + t];
        float p1 = sp[1][threadIdx.x + t];
        phi0 = fmaf(p0, sk[0][t], phi0);
        phi0 = fmaf(p1, sk[1][t], phi0);
        phi1 = fmaf(p0, sk[2][t], phi1);
        phi1 = fmaf(p1, sk[3][t], phi1);
    }
    if (s < L_out) {
        float coef = g_coef[b];
        float th0 = phi0 * coef, th1 = phi1 * coef;
        float c0, s0, c1, s1;
        sincosf(th0, &s0, &c0);
        sincosf(th1, &s1, &c1);
        float2 A0 = a0[s + TRIM];
        float2 A1 = a1[s + TRIM];
        g_buf[0][(long)(b * 2 + 0) * SEQ + s] =
            make_float2(A0.x * c0 - A0.y * s0, A0.x * s0 + A0.y * c0);
        g_buf[0][(long)(b * 2 + 1) * SEQ + s] =
            make_float2(A1.x * c1 - A1.y * s1, A1.x * s1 + A1.y * c1);
    }
}

// ---------------- writeout: buf0 [B*M][Lf] -> out [B,Lf,M,2] ----------------
__global__ void writeout(float* __restrict__ out, int Lf) {
    long i = (long)blockIdx.x * blockDim.x + threadIdx.x;   // over B*Lf*M
    long total = (long)Bz * Lf * NMODES;
    if (i < total) {
        int  m = (int)(i % NMODES);
        long s = (i / NMODES) % Lf;
        int  b = (int)(i / ((long)NMODES * Lf));
        float2 v = g_buf[0][(long)(b * NMODES + m) * SEQ + s];
        out[i * 2 + 0] = v.x;
        out[i * 2 + 1] = v.y;
    }
}

extern "C" void kernel_launch(void* const* d_in, const int* in_sizes, int n_in,
                              void* d_out, int out_size) {
    const float* x_real = (const float*)d_in[0];
    const float* x_imag = (const float*)d_in[1];
    const float* task   = (const float*)d_in[2];
    const float* W1     = (const float*)d_in[3];
    const float* b1     = (const float*)d_in[4];
    const float* W2     = (const float*)d_in[5];
    const float* b2     = (const float*)d_in[6];
    float* out = (float*)d_out;

    disp_kernel<<<dim3(DTAPS, Bz), 128>>>(task);
    nlk_kernel<<<Bz, 128>>>(task, W1, b1, W2, b2);

    long tin = (long)Bz * SEQ * NMODES;
    transpose_in<<<(unsigned)((tin + 255) / 256), 256>>>(x_real, x_imag);

    int L = SEQ;
    for (int step = 0; step < STEPN; step++) {
        int A_len = L - (DTAPS - 1);
        int L_next = A_len - (NTAPS - 1);
        disp_conv<<<dim3((A_len + TILE_OUT - 1) / TILE_OUT, Bz * NMODES), 256>>>(L);
        nl_step<<<dim3((L_next + NTILE - 1) / NTILE, Bz), 256>>>(A_len);
        L = L_next;
    }

    long tout = (long)Bz * L * NMODES;
    writeout<<<(unsigned)((tout + 255) / 256), 256>>>(out, L);
}

// round 4
// speedup vs baseline: 4.5351x; 4.5351x over previous
#include <cuda_runtime.h>
#include <math.h>

#define NMODES 2
#define STEPN  5
#define DTAPS  1001
#define NTAPS  101
#define HID    100
#define TRIM   50
#define Bz     4
#define SEQ    500000
#define FS_NOM 160000000000.0f

#define NFFT   4096
#define NH     2048          // NFFT/2
#define HOP    (NFFT - (DTAPS - 1))   // 3096 valid outputs per FFT block
#define FFT_T  512

#define NTILE  256

// ---------------- scratch (static device memory; no allocations) ----------------
__device__ float2 g_buf[2][Bz * NMODES * SEQ];
__device__ float  g_hr[Bz][DTAPS];
__device__ float  g_hi[Bz][DTAPS];
__device__ float  g_Nk[Bz][4][NTAPS];
__device__ float  g_coef[Bz];
__device__ float2 g_W[NH];            // e^{-2pi i k / NFFT}, k < NFFT/2
__device__ float2 g_G[Bz][NFFT];      // H[-k]/NFFT in DIF bit-reversed order

__device__ __forceinline__ float2 cmulf(float2 a, float2 b) {
    return make_float2(fmaf(a.x, b.x, -(a.y * b.y)),
                       fmaf(a.x, b.y,  (a.y * b.x)));
}

// ---------------- setup: dispersion kernel via direct inverse DFT ----------------
__global__ void disp_kernel(const float* __restrict__ task_info) {
    int m = blockIdx.x;
    int b = blockIdx.y;

    const double c_kms = 299792.458;
    const double FCd   = 299792458.0 / 1.55e-6;
    const double lamb  = c_kms / FCd;
    const double beta2 = -(16.5 * lamb * lamb) / (2.0 * 3.14159265358979323846 * c_kms) / 1000.0;

    float Fsf = task_info[b * 4 + 2];
    float t1  = (float)(2.0 * 3.14159265358979323846) * Fsf;
    float b2h = (float)(beta2 * 0.5);
    float dzf = -400000.0f;

    double sr = 0.0, si = 0.0;
    for (int k = threadIdx.x; k < DTAPS; k += blockDim.x) {
        double fkd = (k <= DTAPS / 2) ? (double)k / (double)DTAPS
                                      : (double)(k - DTAPS) / (double)DTAPS;
        float fkf = (float)fkd;
        float om  = t1 * fkf;
        float phase = (b2h * (om * om)) * dzf;

        float cs, sn;
        sincosf(phase, &sn, &cs);

        int r = (k * m) % DTAPS;
        float ang = (float)((2.0 * 3.14159265358979323846 / (double)DTAPS) * (double)r);
        float st, ct;
        sincosf(ang, &st, &ct);

        sr += (double)(cs * ct + sn * st);
        si += (double)(cs * st - sn * ct);
    }

    __shared__ double rr[128], ri[128];
    rr[threadIdx.x] = sr;
    ri[threadIdx.x] = si;
    __syncthreads();
    for (int o = 64; o > 0; o >>= 1) {
        if (threadIdx.x < o) {
            rr[threadIdx.x] += rr[threadIdx.x + o];
            ri[threadIdx.x] += ri[threadIdx.x + o];
        }
        __syncthreads();
    }
    if (threadIdx.x == 0) {
        int j = (m + DTAPS / 2) % DTAPS;
        g_hr[b][j] = (float)(rr[0] / (double)DTAPS);
        g_hi[b][j] = (float)(ri[0] / (double)DTAPS);
    }
}

// ---------------- setup: nonlinear MLP kernel + coef ----------------
__global__ void nlk_kernel(const float* __restrict__ task_info,
                           const float* __restrict__ W1, const float* __restrict__ b1,
                           const float* __restrict__ W2, const float* __restrict__ b2) {
    int b = blockIdx.x;
    int t = threadIdx.x;
    if (t == 0) {
        float P = 0.001f * powf(10.0f, task_info[b * 4 + 0] / 10.0f) / (float)NMODES;
        g_coef[b] = (float)(0.0016567 * 400000.0) * P;
    }
    if (t < NTAPS) {
        float Fsn = task_info[b * 4 + 2] / FS_NOM;
        float Ts  = 1.0f / Fsn;
        float Ts2 = Ts * Ts;
        float pos = fabsf((float)(t - TRIM)) * 0.005f;
        float inp = pos * Ts2;
        float acc0 = b2[0], acc1 = b2[1], acc2 = b2[2], acc3 = b2[3];
        for (int j = 0; j < HID; j++) {
            float h = fmaf(inp, W1[j], b1[j]);
            h = fmaxf(h, 0.0f);
            acc0 = fmaf(h, W2[j * 4 + 0], acc0);
            acc1 = fmaf(h, W2[j * 4 + 1], acc1);
            acc2 = fmaf(h, W2[j * 4 + 2], acc2);
            acc3 = fmaf(h, W2[j * 4 + 3], acc3);
        }
        float e = expf(-inp);
        g_Nk[b][0][t] = Ts2 * acc0 * e;
        g_Nk[b][1][t] = Ts2 * acc1 * e;
        g_Nk[b][2][t] = Ts2 * acc2 * e;
        g_Nk[b][3][t] = Ts2 * acc3 * e;
    }
}

// ---------------- setup: twiddle table (fp64-accurate) ----------------
__global__ void twiddle_init() {
    int k = blockIdx.x * blockDim.x + threadIdx.x;
    if (k < NH) {
        double ang = -2.0 * 3.14159265358979323846 * (double)k / (double)NFFT;
        double s, c;
        sincos(ang, &s, &c);
        g_W[k] = make_float2((float)c, (float)s);
    }
}

// ---------------- in-smem 4096-pt FFT (radix-2, DIF fwd / DIT inv) ----------------
__device__ __forceinline__ void fft4096_dif(float2* s, int tid) {
#pragma unroll
    for (int m = NH; m >= 1; m >>= 1) {
        int ts = NH / m;
#pragma unroll
        for (int r = 0; r < NH / FFT_T; r++) {
            int q = tid + r * FFT_T;
            int j = q & (m - 1);
            int i = ((q - j) << 1) + j;
            float2 a = s[i], b = s[i + m];
            float2 w = g_W[j * ts];
            float2 d = make_float2(a.x - b.x, a.y - b.y);
            s[i]     = make_float2(a.x + b.x, a.y + b.y);
            s[i + m] = cmulf(d, w);
        }
        __syncthreads();
    }
}

__device__ __forceinline__ void fft4096_dit_inv(float2* s, int tid) {
#pragma unroll
    for (int m = 1; m <= NH; m <<= 1) {
        int ts = NH / m;
#pragma unroll
        for (int r = 0; r < NH / FFT_T; r++) {
            int q = tid + r * FFT_T;
            int j = q & (m - 1);
            int i = ((q - j) << 1) + j;
            float2 a = s[i], b = s[i + m];
            float2 w = g_W[j * ts];
            w.y = -w.y;                       // conj -> e^{+i...}
            float2 t = cmulf(b, w);
            s[i]     = make_float2(a.x + t.x, a.y + t.y);
            s[i + m] = make_float2(a.x - t.x, a.y - t.y);
        }
        __syncthreads();
    }
}

// ---------------- setup: filter spectrum G[k] = H[-k]/NFFT (bit-reversed) ----------------
// Correlation with NON-conjugated complex h needs Y[k] = X[k]*H[-k].
// Identity: conj(FFT(conj(h)))[k] = H[-k]. So FFT conj(h), then conjugate.
__global__ void __launch_bounds__(FFT_T) hspec_kernel() {
    int b = blockIdx.x;
    __shared__ float2 s[NFFT];
    int tid = threadIdx.x;
    for (int i = tid; i < NFFT; i += FFT_T)
        s[i] = (i < DTAPS) ? make_float2(g_hr[b][i], -g_hi[b][i])   // conj(h)
                           : make_float2(0.0f, 0.0f);
    __syncthreads();
    fft4096_dif(s, tid);
    const float inv = 1.0f / (float)NFFT;
    for (int i = tid; i < NFFT; i += FFT_T)
        g_G[b][i] = make_float2(s[i].x * inv, -s[i].y * inv);       // conj(.)/N
}

// ---------------- transpose input [B,SEQ,M] -> buf0 [B*M][SEQ] ----------------
__global__ void transpose_in(const float* __restrict__ xr, const float* __restrict__ xi) {
    long i = (long)blockIdx.x * blockDim.x + threadIdx.x;
    long total = (long)Bz * SEQ * NMODES;
    if (i < total) {
        int  m = (int)(i % NMODES);
        long s = (i / NMODES) % SEQ;
        int  b = (int)(i / ((long)NMODES * SEQ));
        g_buf[0][(long)(b * NMODES + m) * SEQ + s] = make_float2(xr[i], xi[i]);
    }
}

// ---------------- dispersion via FFT overlap-save: buf0 -> buf1 ----------------
__global__ void __launch_bounds__(FFT_T) disp_fft(int L_in) {
    int ch = blockIdx.y;          // b*2+m
    int b  = ch >> 1;
    int tid = threadIdx.x;
    int O = blockIdx.x * HOP;
    int L_out = L_in - (DTAPS - 1);

    __shared__ float2 s[NFFT];    // 32 KB

    const float2* __restrict__ x = &g_buf[0][(long)ch * SEQ];
    for (int i = tid; i < NFFT; i += FFT_T) {
        int g = O + i;
        s[i] = (g < L_in) ? x[g] : make_float2(0.0f, 0.0f);
    }
    __syncthreads();

    fft4096_dif(s, tid);

    const float2* __restrict__ G = g_G[b];
    for (int i = tid; i < NFFT; i += FFT_T)
        s[i] = cmulf(s[i], G[i]);
    __syncthreads();

    fft4096_dit_inv(s, tid);

    float2* __restrict__ ao = &g_buf[1][(long)ch * SEQ];
    for (int i = tid; i < HOP; i += FFT_T) {
        int o = O + i;
        if (o < L_out) ao[o] = s[i];
    }
}

// ---------------- nonlinear: power conv + rotation, buf1 -> buf0 ----------------
__global__ void __launch_bounds__(256) nl_step(int A_len) {
    int b = blockIdx.y;
    int L_out = A_len - (NTAPS - 1);
    int base = blockIdx.x * NTILE;

    __shared__ float sp[2][NTILE + NTAPS - 1];
    __shared__ float sk[4][NTAPS];

    const float2* __restrict__ a0 = &g_buf[1][(long)(b * 2 + 0) * SEQ];
    const float2* __restrict__ a1 = &g_buf[1][(long)(b * 2 + 1) * SEQ];

    for (int i = threadIdx.x; i < NTILE + NTAPS - 1; i += 256) {
        int g = base + i;
        float2 v0 = (g < A_len) ? a0[g] : make_float2(0.f, 0.f);
        float2 v1 = (g < A_len) ? a1[g] : make_float2(0.f, 0.f);
        sp[0][i] = v0.x * v0.x + v0.y * v0.y;
        sp[1][i] = v1.x * v1.x + v1.y * v1.y;
    }
    for (int i = threadIdx.x; i < 4 * NTAPS; i += 256)
        sk[i / NTAPS][i % NTAPS] = g_Nk[b][i / NTAPS][i % NTAPS];
    __syncthreads();

    int s = base + threadIdx.x;
    float phi0 = 0.f, phi1 = 0.f;
#pragma unroll 4
    for (int t = 0; t < NTAPS; t++) {
        float p0 = sp[0][threadIdx.x + t];
        float p1 = sp[1][threadIdx.x + t];
        phi0 = fmaf(p0, sk[0][t], phi0);
        phi0 = fmaf(p1, sk[1][t], phi0);
        phi1 = fmaf(p0, sk[2][t], phi1);
        phi1 = fmaf(p1, sk[3][t], phi1);
    }
    if (s < L_out) {
        float coef = g_coef[b];
        float th0 = phi0 * coef, th1 = phi1 * coef;
        float c0, s0, c1, s1;
        sincosf(th0, &s0, &c0);
        sincosf(th1, &s1, &c1);
        float2 A0 = a0[s + TRIM];
        float2 A1 = a1[s + TRIM];
        g_buf[0][(long)(b * 2 + 0) * SEQ + s] =
            make_float2(A0.x * c0 - A0.y * s0, A0.x * s0 + A0.y * c0);
        g_buf[0][(long)(b * 2 + 1) * SEQ + s] =
            make_float2(A1.x * c1 - A1.y * s1, A1.x * s1 + A1.y * c1);
    }
}

// ---------------- writeout: buf0 [B*M][Lf] -> out [B,Lf,M,2] ----------------
__global__ void writeout(float* __restrict__ out, int Lf) {
    long i = (long)blockIdx.x * blockDim.x + threadIdx.x;
    long total = (long)Bz * Lf * NMODES;
    if (i < total) {
        int  m = (int)(i % NMODES);
        long s = (i / NMODES) % Lf;
        int  b = (int)(i / ((long)NMODES * Lf));
        float2 v = g_buf[0][(long)(b * NMODES + m) * SEQ + s];
        out[i * 2 + 0] = v.x;
        out[i * 2 + 1] = v.y;
    }
}

extern "C" void kernel_launch(void* const* d_in, const int* in_sizes, int n_in,
                              void* d_out, int out_size) {
    const float* x_real = (const float*)d_in[0];
    const float* x_imag = (const float*)d_in[1];
    const float* task   = (const float*)d_in[2];
    const float* W1     = (const float*)d_in[3];
    const float* b1     = (const float*)d_in[4];
    const float* W2     = (const float*)d_in[5];
    const float* b2     = (const float*)d_in[6];
    float* out = (float*)d_out;

    disp_kernel<<<dim3(DTAPS, Bz), 128>>>(task);
    nlk_kernel<<<Bz, 128>>>(task, W1, b1, W2, b2);
    twiddle_init<<<(NH + 255) / 256, 256>>>();
    hspec_kernel<<<Bz, FFT_T>>>();

    long tin = (long)Bz * SEQ * NMODES;
    transpose_in<<<(unsigned)((tin + 255) / 256), 256>>>(x_real, x_imag);

    int L = SEQ;
    for (int step = 0; step < STEPN; step++) {
        int A_len = L - (DTAPS - 1);
        int L_next = A_len - (NTAPS - 1);
        disp_fft<<<dim3((A_len + HOP - 1) / HOP, Bz * NMODES), FFT_T>>>(L);
        nl_step<<<dim3((L_next + NTILE - 1) / NTILE, Bz), 256>>>(A_len);
        L = L_next;
    }

    long tout = (long)Bz * L * NMODES;
    writeout<<<(unsigned)((tout + 255) / 256), 256>>>(out, L);
}

// round 5
// speedup vs baseline: 5.0627x; 1.1163x over previous
#include <cuda_runtime.h>
#include <math.h>

#define NMODES 2
#define STEPN  5
#define DTAPS  1001
#define NTAPS  101
#define HID    100
#define TRIM   50
#define Bz     4
#define SEQ    500000
#define FS_NOM 160000000000.0f

#define NFFT   4096
#define NW     3072          // twiddle table size (max index 3*j*ts < 3072)
#define HOP    (NFFT - (DTAPS - 1))   // 3096 valid outputs per FFT block
#define FFT_T  512

#define NTILE  512

// ---------------- scratch (static device memory; no allocations) ----------------
__device__ float2 g_buf[2][Bz * NMODES * SEQ];
__device__ float  g_hr[Bz][DTAPS];
__device__ float  g_hi[Bz][DTAPS];
__device__ float  g_Nk[Bz][4][NTAPS];   // coef pre-folded
__device__ float2 g_W[NW];              // e^{-2pi i k / NFFT}
__device__ float2 g_G[Bz][NFFT];        // H[-k]/NFFT in radix-4 DIF digit-reversed order

__device__ __forceinline__ float2 cmulf(float2 a, float2 b) {
    return make_float2(fmaf(a.x, b.x, -(a.y * b.y)),
                       fmaf(a.x, b.y,  (a.y * b.x)));
}
// a * conj(w)
__device__ __forceinline__ float2 cmulc(float2 a, float2 w) {
    return make_float2(fmaf(a.x, w.x,  (a.y * w.y)),
                       fmaf(a.y, w.x, -(a.x * w.y)));
}

// ---------------- setup: dispersion kernel via direct inverse DFT ----------------
__global__ void disp_kernel(const float* __restrict__ task_info) {
    int m = blockIdx.x;
    int b = blockIdx.y;

    const double c_kms = 299792.458;
    const double FCd   = 299792458.0 / 1.55e-6;
    const double lamb  = c_kms / FCd;
    const double beta2 = -(16.5 * lamb * lamb) / (2.0 * 3.14159265358979323846 * c_kms) / 1000.0;

    float Fsf = task_info[b * 4 + 2];
    float t1  = (float)(2.0 * 3.14159265358979323846) * Fsf;
    float b2h = (float)(beta2 * 0.5);
    float dzf = -400000.0f;

    double sr = 0.0, si = 0.0;
    for (int k = threadIdx.x; k < DTAPS; k += blockDim.x) {
        double fkd = (k <= DTAPS / 2) ? (double)k / (double)DTAPS
                                      : (double)(k - DTAPS) / (double)DTAPS;
        float fkf = (float)fkd;
        float om  = t1 * fkf;
        float phase = (b2h * (om * om)) * dzf;

        float cs, sn;
        sincosf(phase, &sn, &cs);

        int r = (k * m) % DTAPS;
        float ang = (float)((2.0 * 3.14159265358979323846 / (double)DTAPS) * (double)r);
        float st, ct;
        sincosf(ang, &st, &ct);

        sr += (double)(cs * ct + sn * st);
        si += (double)(cs * st - sn * ct);
    }

    __shared__ double rr[128], ri[128];
    rr[threadIdx.x] = sr;
    ri[threadIdx.x] = si;
    __syncthreads();
    for (int o = 64; o > 0; o >>= 1) {
        if (threadIdx.x < o) {
            rr[threadIdx.x] += rr[threadIdx.x + o];
            ri[threadIdx.x] += ri[threadIdx.x + o];
        }
        __syncthreads();
    }
    if (threadIdx.x == 0) {
        int j = (m + DTAPS / 2) % DTAPS;
        g_hr[b][j] = (float)(rr[0] / (double)DTAPS);
        g_hi[b][j] = (float)(ri[0] / (double)DTAPS);
    }
}

// ---------------- setup: nonlinear MLP kernel (coef folded in) ----------------
__global__ void nlk_kernel(const float* __restrict__ task_info,
                           const float* __restrict__ W1, const float* __restrict__ b1,
                           const float* __restrict__ W2, const float* __restrict__ b2) {
    int b = blockIdx.x;
    int t = threadIdx.x;
    if (t < NTAPS) {
        float P = 0.001f * powf(10.0f, task_info[b * 4 + 0] / 10.0f) / (float)NMODES;
        float coef = (float)(0.0016567 * 400000.0) * P;
        float Fsn = task_info[b * 4 + 2] / FS_NOM;
        float Ts  = 1.0f / Fsn;
        float Ts2 = Ts * Ts;
        float pos = fabsf((float)(t - TRIM)) * 0.005f;
        float inp = pos * Ts2;
        float acc0 = b2[0], acc1 = b2[1], acc2 = b2[2], acc3 = b2[3];
        for (int j = 0; j < HID; j++) {
            float h = fmaf(inp, W1[j], b1[j]);
            h = fmaxf(h, 0.0f);
            acc0 = fmaf(h, W2[j * 4 + 0], acc0);
            acc1 = fmaf(h, W2[j * 4 + 1], acc1);
            acc2 = fmaf(h, W2[j * 4 + 2], acc2);
            acc3 = fmaf(h, W2[j * 4 + 3], acc3);
        }
        float e = expf(-inp) * coef;
        g_Nk[b][0][t] = Ts2 * acc0 * e;
        g_Nk[b][1][t] = Ts2 * acc1 * e;
        g_Nk[b][2][t] = Ts2 * acc2 * e;
        g_Nk[b][3][t] = Ts2 * acc3 * e;
    }
}

// ---------------- setup: twiddle table (fp64-accurate) ----------------
__global__ void twiddle_init() {
    int k = blockIdx.x * blockDim.x + threadIdx.x;
    if (k < NW) {
        double ang = -2.0 * 3.14159265358979323846 * (double)k / (double)NFFT;
        double s, c;
        sincos(ang, &s, &c);
        g_W[k] = make_float2((float)c, (float)s);
    }
}

// ---------------- in-smem 4096-pt radix-4 FFT (DIF fwd / mirrored DIT inv) ----------------
// DIF stage: b[j+q*m] = F4_row_q(a) * W^{q*j}, W = e^{-2pi i/L}. Output ends
// base-4 digit-reversed; pointwise product valid since G uses the same DIF;
// inverse DIT below is the exact stage-mirrored algebraic inverse (x4 per
// stage, total 4^6 = NFFT, folded into G).
__device__ __forceinline__ void fft4096_dif4(float2* s, int tid) {
#pragma unroll
    for (int L = NFFT; L >= 4; L >>= 2) {
        int m  = L >> 2;
        int ts = NFFT / L;
#pragma unroll
        for (int r = 0; r < NFFT / 4 / FFT_T; r++) {
            int q = tid + r * FFT_T;
            int j = q & (m - 1);
            int i = ((q - j) << 2) + j;
            float2 a0 = s[i], a1 = s[i + m], a2 = s[i + 2 * m], a3 = s[i + 3 * m];
            float2 t0 = make_float2(a0.x + a2.x, a0.y + a2.y);
            float2 t2 = make_float2(a0.x - a2.x, a0.y - a2.y);
            float2 t1 = make_float2(a1.x + a3.x, a1.y + a3.y);
            float2 t3 = make_float2(a1.x - a3.x, a1.y - a3.y);
            float2 b0 = make_float2(t0.x + t1.x, t0.y + t1.y);
            float2 b2v = make_float2(t0.x - t1.x, t0.y - t1.y);
            float2 b1 = make_float2(t2.x + t3.y, t2.y - t3.x);   // t2 - i*t3
            float2 b3 = make_float2(t2.x - t3.y, t2.y + t3.x);   // t2 + i*t3
            s[i] = b0;
            s[i + m]     = cmulf(b1,  g_W[j * ts]);
            s[i + 2 * m] = cmulf(b2v, g_W[2 * j * ts]);
            s[i + 3 * m] = cmulf(b3,  g_W[3 * j * ts]);
        }
        __syncthreads();
    }
}

__device__ __forceinline__ void fft4096_dit4_inv(float2* s, int tid) {
#pragma unroll
    for (int L = 4; L <= NFFT; L <<= 2) {
        int m  = L >> 2;
        int ts = NFFT / L;
#pragma unroll
        for (int r = 0; r < NFFT / 4 / FFT_T; r++) {
            int q = tid + r * FFT_T;
            int j = q & (m - 1);
            int i = ((q - j) << 2) + j;
            float2 c0 = s[i];
            float2 c1 = cmulc(s[i + m],     g_W[j * ts]);
            float2 c2 = cmulc(s[i + 2 * m], g_W[2 * j * ts]);
            float2 c3 = cmulc(s[i + 3 * m], g_W[3 * j * ts]);
            float2 u0 = make_float2(c0.x + c2.x, c0.y + c2.y);
            float2 u2 = make_float2(c0.x - c2.x, c0.y - c2.y);
            float2 u1 = make_float2(c1.x + c3.x, c1.y + c3.y);
            float2 u3 = make_float2(c1.x - c3.x, c1.y - c3.y);
            s[i]         = make_float2(u0.x + u1.x, u0.y + u1.y);
            s[i + 2 * m] = make_float2(u0.x - u1.x, u0.y - u1.y);
            s[i + m]     = make_float2(u2.x - u3.y, u2.y + u3.x); // u2 + i*u3
            s[i + 3 * m] = make_float2(u2.x + u3.y, u2.y - u3.x); // u2 - i*u3
        }
        __syncthreads();
    }
}

// ---------------- setup: filter spectrum G[k] = H[-k]/NFFT (digit-reversed) ----------------
// Correlation with NON-conjugated complex h needs Y[k] = X[k]*H[-k].
// Identity: conj(FFT(conj(h)))[k] = H[-k]. So FFT conj(h), then conjugate.
__global__ void __launch_bounds__(FFT_T) hspec_kernel() {
    int b = blockIdx.x;
    __shared__ float2 s[NFFT];
    int tid = threadIdx.x;
    for (int i = tid; i < NFFT; i += FFT_T)
        s[i] = (i < DTAPS) ? make_float2(g_hr[b][i], -g_hi[b][i])   // conj(h)
                           : make_float2(0.0f, 0.0f);
    __syncthreads();
    fft4096_dif4(s, tid);
    const float inv = 1.0f / (float)NFFT;
    for (int i = tid; i < NFFT; i += FFT_T)
        g_G[b][i] = make_float2(s[i].x * inv, -s[i].y * inv);       // conj(.)/N
}

// ---------------- transpose input [B,SEQ,M] -> buf0 [B*M][SEQ] ----------------
__global__ void transpose_in(const float* __restrict__ xr, const float* __restrict__ xi) {
    long i = (long)blockIdx.x * blockDim.x + threadIdx.x;
    long total = (long)Bz * SEQ * NMODES;
    if (i < total) {
        int  m = (int)(i % NMODES);
        long s = (i / NMODES) % SEQ;
        int  b = (int)(i / ((long)NMODES * SEQ));
        g_buf[0][(long)(b * NMODES + m) * SEQ + s] = make_float2(xr[i], xi[i]);
    }
}

// ---------------- dispersion via FFT overlap-save: buf0 -> buf1 ----------------
__global__ void __launch_bounds__(FFT_T) disp_fft(int L_in) {
    int ch = blockIdx.y;          // b*2+m
    int b  = ch >> 1;
    int tid = threadIdx.x;
    int O = blockIdx.x * HOP;
    int L_out = L_in - (DTAPS - 1);

    __shared__ float2 s[NFFT];    // 32 KB

    const float2* __restrict__ x = &g_buf[0][(long)ch * SEQ];
    for (int i = tid; i < NFFT; i += FFT_T) {
        int g = O + i;
        s[i] = (g < L_in) ? x[g] : make_float2(0.0f, 0.0f);
    }
    __syncthreads();

    fft4096_dif4(s, tid);

    const float2* __restrict__ G = g_G[b];
    for (int i = tid; i < NFFT; i += FFT_T)
        s[i] = cmulf(s[i], G[i]);
    __syncthreads();

    fft4096_dit4_inv(s, tid);

    float2* __restrict__ ao = &g_buf[1][(long)ch * SEQ];
    for (int i = tid; i < HOP; i += FFT_T) {
        int o = O + i;
        if (o < L_out) ao[o] = s[i];
    }
}

// ---------------- nonlinear: power conv + rotation, buf1 -> buf0 (or out) ----------------
__global__ void __launch_bounds__(NTILE) nl_step(int A_len, float4* __restrict__ outp, int Lf) {
    int b = blockIdx.y;
    int L_out = A_len - (NTAPS - 1);
    int base = blockIdx.x * NTILE;

    __shared__ float2 sp[NTILE + NTAPS - 1];   // (p0, p1) per sample
    __shared__ float4 sk[NTAPS];               // 4 mode-pair taps, coef folded

    const float2* __restrict__ a0 = &g_buf[1][(long)(b * 2 + 0) * SEQ];
    const float2* __restrict__ a1 = &g_buf[1][(long)(b * 2 + 1) * SEQ];

    for (int i = threadIdx.x; i < NTILE + NTAPS - 1; i += NTILE) {
        int g = base + i;
        float2 v0 = (g < A_len) ? a0[g] : make_float2(0.f, 0.f);
        float2 v1 = (g < A_len) ? a1[g] : make_float2(0.f, 0.f);
        sp[i] = make_float2(fmaf(v0.x, v0.x, v0.y * v0.y),
                            fmaf(v1.x, v1.x, v1.y * v1.y));
    }
    if (threadIdx.x < NTAPS) {
        int t = threadIdx.x;
        sk[t] = make_float4(g_Nk[b][0][t], g_Nk[b][1][t], g_Nk[b][2][t], g_Nk[b][3][t]);
    }
    __syncthreads();

    int s = base + threadIdx.x;
    float phi0 = 0.f, phi1 = 0.f;
#pragma unroll 4
    for (int t = 0; t < NTAPS; t++) {
        float2 p = sp[threadIdx.x + t];
        float4 k = sk[t];
        phi0 = fmaf(p.x, k.x, phi0);
        phi0 = fmaf(p.y, k.y, phi0);
        phi1 = fmaf(p.x, k.z, phi1);
        phi1 = fmaf(p.y, k.w, phi1);
    }
    if (s < L_out) {
        float c0, s0, c1, s1;
        sincosf(phi0, &s0, &c0);
        sincosf(phi1, &s1, &c1);
        float2 A0 = a0[s + TRIM];
        float2 A1 = a1[s + TRIM];
        float2 r0 = make_float2(A0.x * c0 - A0.y * s0, A0.x * s0 + A0.y * c0);
        float2 r1 = make_float2(A1.x * c1 - A1.y * s1, A1.x * s1 + A1.y * c1);
        if (outp) {
            // out layout [B, Lf, M, 2]: one float4 per (b, s)
            outp[(long)b * Lf + s] = make_float4(r0.x, r0.y, r1.x, r1.y);
        } else {
            g_buf[0][(long)(b * 2 + 0) * SEQ + s] = r0;
            g_buf[0][(long)(b * 2 + 1) * SEQ + s] = r1;
        }
    }
}

extern "C" void kernel_launch(void* const* d_in, const int* in_sizes, int n_in,
                              void* d_out, int out_size) {
    const float* x_real = (const float*)d_in[0];
    const float* x_imag = (const float*)d_in[1];
    const float* task   = (const float*)d_in[2];
    const float* W1     = (const float*)d_in[3];
    const float* b1     = (const float*)d_in[4];
    const float* W2     = (const float*)d_in[5];
    const float* b2     = (const float*)d_in[6];

    disp_kernel<<<dim3(DTAPS, Bz), 128>>>(task);
    nlk_kernel<<<Bz, 128>>>(task, W1, b1, W2, b2);
    twiddle_init<<<(NW + 255) / 256, 256>>>();
    hspec_kernel<<<Bz, FFT_T>>>();

    long tin = (long)Bz * SEQ * NMODES;
    transpose_in<<<(unsigned)((tin + 255) / 256), 256>>>(x_real, x_imag);

    int L = SEQ;
    for (int step = 0; step < STEPN; step++) {
        int A_len = L - (DTAPS - 1);
        int L_next = A_len - (NTAPS - 1);
        bool last = (step == STEPN - 1);
        disp_fft<<<dim3((A_len + HOP - 1) / HOP, Bz * NMODES), FFT_T>>>(L);
        nl_step<<<dim3((L_next + NTILE - 1) / NTILE, Bz), NTILE>>>(
            A_len, last ? (float4*)d_out : nullptr, L_next);
        L = L_next;
    }
}